// round 13
// baseline (speedup 1.0000x reference)
#include <cuda_runtime.h>

// Problem constants
#define B     256
#define T     512
#define NPOS  128
#define NACT  32
#define DIN   160            // NPOS + NACT
#define H     512
#define DTOT  672            // DIN + H
#define NCTA  128            // recurrent grid size (must be < #SMs for residency)
#define HC    4              // hidden units per CTA = H / NCTA
#define NG    16             // gate rows per CTA = 4 * HC

// ---------------------------------------------------------------------------
// Device scratch (static allocation — no cudaMalloc allowed)
// ---------------------------------------------------------------------------
__device__ float g_XT[(size_t)T * DIN * B];        // x transposed: [t][d][b]   (84 MB)
__device__ float g_hall[(size_t)(T + 1) * H * B];  // h history:    [t][j][b]   (269 MB)
__device__ unsigned int          g_count;          // barrier arrive counter
__device__ volatile unsigned int g_gen;            // barrier generation flag

// ---------------------------------------------------------------------------
// Packed f32x2 helpers (FFMA2 — 2x fp32 FMA throughput vs 3-reg FFMA on sm_103a)
// ---------------------------------------------------------------------------
__device__ __forceinline__ unsigned long long pack2(float lo, float hi) {
    unsigned long long r;
    asm("mov.b64 %0, {%1, %2};" : "=l"(r) : "f"(lo), "f"(hi));
    return r;
}
__device__ __forceinline__ float2 unpack2(unsigned long long v) {
    float2 r;
    asm("mov.b64 {%0, %1}, %2;" : "=f"(r.x), "=f"(r.y) : "l"(v));
    return r;
}
__device__ __forceinline__ void fma2(unsigned long long& d,
                                     unsigned long long a,
                                     unsigned long long w) {
    asm("fma.rn.f32x2 %0, %1, %2, %0;" : "+l"(d) : "l"(a), "l"(w));
}

__device__ __forceinline__ float sigm(float x) {
    return 1.0f / (1.0f + expf(-x));
}

// ---------------------------------------------------------------------------
// Kernel 1: prep
//   - transpose [obs|act] into g_XT[t][d][b] (coalesced reads & writes via tile)
//   - transpose h0 into g_hall[0][j][b]
//   - reset grid barrier state
// Grid: 512 blocks (one per t; blockIdx also doubles as hidden row j for h0),
// 256 threads.
// ---------------------------------------------------------------------------
__global__ void prep_kernel(const float* __restrict__ obs,
                            const float* __restrict__ act,
                            const float* __restrict__ h0) {
    const int t  = blockIdx.x;
    const int tx = threadIdx.x & 31;
    const int ty = threadIdx.x >> 5;   // 0..7
    __shared__ float tile[32][33];

    for (int b0 = 0; b0 < B; b0 += 32) {
        // observation: 4 d-tiles of 32
        for (int d0 = 0; d0 < NPOS; d0 += 32) {
            #pragma unroll
            for (int r = 0; r < 32; r += 8)
                tile[ty + r][tx] =
                    obs[((size_t)(b0 + ty + r) * T + t) * NPOS + d0 + tx];
            __syncthreads();
            #pragma unroll
            for (int r = 0; r < 32; r += 8)
                g_XT[((size_t)t * DIN + d0 + ty + r) * B + b0 + tx] =
                    tile[tx][ty + r];
            __syncthreads();
        }
        // action: one d-tile of 32 -> XT rows 128..159
        #pragma unroll
        for (int r = 0; r < 32; r += 8)
            tile[ty + r][tx] =
                act[((size_t)(b0 + ty + r) * T + t) * NACT + tx];
        __syncthreads();
        #pragma unroll
        for (int r = 0; r < 32; r += 8)
            g_XT[((size_t)t * DIN + NPOS + ty + r) * B + b0 + tx] =
                tile[tx][ty + r];
        __syncthreads();
    }

    // h0 transpose: block t handles hidden row j = t (T == H == 512)
    g_hall[(size_t)t * B + threadIdx.x] = h0[(size_t)threadIdx.x * H + t];

    if (t == 0 && threadIdx.x == 0) {
        g_count = 0u;
        g_gen   = 0u;
    }
}

// ---------------------------------------------------------------------------
// Grid barrier (sense via monotone generation counter). All NCTA blocks are
// wave-1 resident (NCTA=128 < 148 SMs, 1 block/SM possible), so spinning is
// deadlock-free. Producer h-stores are made L2-visible by __syncthreads +
// thread-0 __threadfence before arrive; consumers read h via __ldcg (L2).
// ---------------------------------------------------------------------------
__device__ __forceinline__ void grid_barrier(unsigned int target) {
    __syncthreads();
    if (threadIdx.x == 0) {
        __threadfence();
        unsigned int prev = atomicAdd(&g_count, 1u);
        if (prev == NCTA - 1) {
            g_count = 0u;
            __threadfence();
            g_gen = target;           // release
        } else {
            while (g_gen < target) __nanosleep(64);
            __threadfence();          // acquire
        }
    }
    __syncthreads();
}

// ---------------------------------------------------------------------------
// Kernel 2: persistent recurrent LSTM.
// Each CTA owns HC=4 hidden units (NG=16 gate rows) for ALL 256 batches.
// Weights for those rows (672 cols) live in SMEM for the whole kernel.
// Thread = batch index. Per step: 672 k-iters x 8 packed FMA2 per thread.
// h exchanged through g_hall with one grid barrier per step.
// ---------------------------------------------------------------------------
__global__ void __launch_bounds__(256)
lstm_rec_kernel(const float* __restrict__ Wih,
                const float* __restrict__ Whh,
                const float* __restrict__ bih,
                const float* __restrict__ bhh,
                const float* __restrict__ c0) {
    // wshv[k*4 + m] holds gate-row pairs (4m,4m+1) and (4m+2,4m+3) for column k
    __shared__ ulonglong2 wshv[DTOT * 4];   // 43008 B
    __shared__ float      csh[HC][B];       //  4096 B
    __shared__ float      bsh[NG];          //    64 B

    const int b  = threadIdx.x;             // batch index
    const int j0 = blockIdx.x * HC;         // first hidden unit of this CTA

    // ---- one-time weight load into SMEM: wf[k*16 + u] = W_row(u)[k] ----
    // u = gate*4 + unit;  gate row r = gate*H + j0 + unit
    {
        float* wf = reinterpret_cast<float*>(wshv);
        for (int idx = threadIdx.x; idx < DTOT * NG; idx += 256) {
            int k = idx >> 4;
            int u = idx & 15;
            int r = (u >> 2) * H + j0 + (u & 3);
            float w = (k < DIN) ? Wih[(size_t)r * DIN + k]
                                : Whh[(size_t)r * H + (k - DIN)];
            wf[idx] = w;
        }
    }
    if (threadIdx.x < NG) {
        int u = threadIdx.x;
        int r = (u >> 2) * H + j0 + (u & 3);
        bsh[u] = bih[r] + bhh[r];
    }
    #pragma unroll
    for (int u = 0; u < HC; ++u)
        csh[u][b] = c0[(size_t)b * H + j0 + u];
    __syncthreads();

    // ---- time loop ----
    for (int t = 0; t < T; ++t) {
        unsigned long long acc[8];          // pairs: u = 2q, 2q+1
        #pragma unroll
        for (int q = 0; q < 8; ++q)
            acc[q] = pack2(bsh[2 * q], bsh[2 * q + 1]);

        const float* xp = g_XT  + (size_t)t * DIN * B + b;
        const float* hp = g_hall + (size_t)t * H   * B + b;

        // input part: k = 0..159
        #pragma unroll 8
        for (int k = 0; k < DIN; ++k) {
            float v = xp[k * B];
            unsigned long long v2 = pack2(v, v);
            const ulonglong2* w = &wshv[k * 4];
            #pragma unroll
            for (int m = 0; m < 4; ++m) {
                ulonglong2 ww = w[m];
                fma2(acc[2 * m],     v2, ww.x);
                fma2(acc[2 * m + 1], v2, ww.y);
            }
        }
        // recurrent part: k = 0..511 (h read L2-fresh via __ldcg)
        #pragma unroll 8
        for (int k = 0; k < H; ++k) {
            float v = __ldcg(hp + k * B);
            unsigned long long v2 = pack2(v, v);
            const ulonglong2* w = &wshv[(DIN + k) * 4];
            #pragma unroll
            for (int m = 0; m < 4; ++m) {
                ulonglong2 ww = w[m];
                fma2(acc[2 * m],     v2, ww.x);
                fma2(acc[2 * m + 1], v2, ww.y);
            }
        }

        // gate activations + state update
        float iv[4], fv[4], gv[4], ov[4];
        {
            float2 p;
            p = unpack2(acc[0]); iv[0] = p.x; iv[1] = p.y;
            p = unpack2(acc[1]); iv[2] = p.x; iv[3] = p.y;
            p = unpack2(acc[2]); fv[0] = p.x; fv[1] = p.y;
            p = unpack2(acc[3]); fv[2] = p.x; fv[3] = p.y;
            p = unpack2(acc[4]); gv[0] = p.x; gv[1] = p.y;
            p = unpack2(acc[5]); gv[2] = p.x; gv[3] = p.y;
            p = unpack2(acc[6]); ov[0] = p.x; ov[1] = p.y;
            p = unpack2(acc[7]); ov[2] = p.x; ov[3] = p.y;
        }
        float* outp = g_hall + (size_t)(t + 1) * H * B + b;
        #pragma unroll
        for (int u = 0; u < HC; ++u) {
            float i_ = sigm(iv[u]);
            float f_ = sigm(fv[u]);
            float gg = tanhf(gv[u]);
            float o_ = sigm(ov[u]);
            float c  = f_ * csh[u][b] + i_ * gg;
            float h  = o_ * tanhf(c);
            csh[u][b] = c;
            outp[(j0 + u) * B] = h;
        }

        grid_barrier((unsigned int)(t + 1));
    }
}

// ---------------------------------------------------------------------------
// Kernel 3: y[b][t] = h_{t+1-slot} . W_out + b_out   (fully parallel GEMV)
// Grid: 512 blocks (one per t), 256 threads (one per b). Deterministic.
// ---------------------------------------------------------------------------
__global__ void yfinal_kernel(const float* __restrict__ wout,
                              const float* __restrict__ bout,
                              float* __restrict__ y) {
    __shared__ float ws[H];
    const int t = blockIdx.x;
    const int b = threadIdx.x;
    for (int j = threadIdx.x; j < H; j += 256) ws[j] = wout[j];
    __syncthreads();

    float s = bout[0];
    const float* hp = g_hall + (size_t)(t + 1) * H * B + b;
    #pragma unroll 8
    for (int j = 0; j < H; ++j)
        s += hp[(size_t)j * B] * ws[j];
    y[(size_t)b * T + t] = s;
}

// ---------------------------------------------------------------------------
// Launch
// ---------------------------------------------------------------------------
extern "C" void kernel_launch(void* const* d_in, const int* in_sizes, int n_in,
                              void* d_out, int out_size) {
    const float* obs  = (const float*)d_in[0];
    const float* act  = (const float*)d_in[1];
    const float* Wih  = (const float*)d_in[2];
    const float* Whh  = (const float*)d_in[3];
    const float* bih  = (const float*)d_in[4];
    const float* bhh  = (const float*)d_in[5];
    const float* Wout = (const float*)d_in[6];
    const float* bout = (const float*)d_in[7];
    const float* h0   = (const float*)d_in[8];
    const float* c0   = (const float*)d_in[9];
    float* y = (float*)d_out;

    prep_kernel<<<T, 256>>>(obs, act, h0);
    lstm_rec_kernel<<<NCTA, 256>>>(Wih, Whh, bih, bhh, c0);
    yfinal_kernel<<<T, 256>>>(Wout, bout, y);
}

// round 14
// speedup vs baseline: 1.0090x; 1.0090x over previous
#include <cuda_runtime.h>

// Problem constants
#define B     256
#define T     512
#define NPOS  128
#define NACT  32
#define DIN   160            // NPOS + NACT
#define H     512
#define DTOT  672            // DIN + H
#define NCTA  128            // recurrent grid size (must be < #SMs for residency)
#define HC    4              // hidden units per CTA = H / NCTA
#define NG    16             // gate rows per CTA = 4 * HC
#define KSPLIT 336           // k per half (DIN + 176 = 336 ; 512-176 = 336)

// ---------------------------------------------------------------------------
// Device scratch (static allocation — no cudaMalloc allowed)
// ---------------------------------------------------------------------------
__device__ float g_XT[(size_t)T * DIN * B];        // x transposed: [t][d][b]   (84 MB)
__device__ float g_hall[(size_t)(T + 1) * H * B];  // h history:    [t][j][b]   (269 MB)
__device__ unsigned int          g_count;          // barrier arrive counter
__device__ volatile unsigned int g_gen;            // barrier generation flag

// ---------------------------------------------------------------------------
// Packed f32x2 helpers (FFMA2 — 2x fp32 FMA throughput vs 3-reg FFMA on sm_103a)
// ---------------------------------------------------------------------------
__device__ __forceinline__ unsigned long long pack2(float lo, float hi) {
    unsigned long long r;
    asm("mov.b64 %0, {%1, %2};" : "=l"(r) : "f"(lo), "f"(hi));
    return r;
}
__device__ __forceinline__ float2 unpack2(unsigned long long v) {
    float2 r;
    asm("mov.b64 {%0, %1}, %2;" : "=f"(r.x), "=f"(r.y) : "l"(v));
    return r;
}
__device__ __forceinline__ void fma2(unsigned long long& d,
                                     unsigned long long a,
                                     unsigned long long w) {
    asm("fma.rn.f32x2 %0, %1, %2, %0;" : "+l"(d) : "l"(a), "l"(w));
}

__device__ __forceinline__ float sigm(float x) {
    return 1.0f / (1.0f + expf(-x));
}

// ---------------------------------------------------------------------------
// Kernel 1: prep — transpose inputs, transpose h0, reset barrier state.
// ---------------------------------------------------------------------------
__global__ void prep_kernel(const float* __restrict__ obs,
                            const float* __restrict__ act,
                            const float* __restrict__ h0) {
    const int t  = blockIdx.x;
    const int tx = threadIdx.x & 31;
    const int ty = threadIdx.x >> 5;   // 0..7
    __shared__ float tile[32][33];

    for (int b0 = 0; b0 < B; b0 += 32) {
        for (int d0 = 0; d0 < NPOS; d0 += 32) {
            #pragma unroll
            for (int r = 0; r < 32; r += 8)
                tile[ty + r][tx] =
                    obs[((size_t)(b0 + ty + r) * T + t) * NPOS + d0 + tx];
            __syncthreads();
            #pragma unroll
            for (int r = 0; r < 32; r += 8)
                g_XT[((size_t)t * DIN + d0 + ty + r) * B + b0 + tx] =
                    tile[tx][ty + r];
            __syncthreads();
        }
        #pragma unroll
        for (int r = 0; r < 32; r += 8)
            tile[ty + r][tx] =
                act[((size_t)(b0 + ty + r) * T + t) * NACT + tx];
        __syncthreads();
        #pragma unroll
        for (int r = 0; r < 32; r += 8)
            g_XT[((size_t)t * DIN + NPOS + ty + r) * B + b0 + tx] =
                tile[tx][ty + r];
        __syncthreads();
    }

    // h0 transpose: block t handles hidden row j = t (T == H == 512)
    g_hall[(size_t)t * B + threadIdx.x] = h0[(size_t)threadIdx.x * H + t];

    if (t == 0 && threadIdx.x == 0) {
        g_count = 0u;
        g_gen   = 0u;
    }
}

// ---------------------------------------------------------------------------
// Grid barrier (monotone generation). 128 CTAs, all wave-1 resident.
// ---------------------------------------------------------------------------
__device__ __forceinline__ void grid_barrier(unsigned int target) {
    __syncthreads();
    if (threadIdx.x == 0) {
        __threadfence();
        unsigned int prev = atomicAdd(&g_count, 1u);
        if (prev == NCTA - 1) {
            g_count = 0u;
            __threadfence();
            g_gen = target;           // release
        } else {
            while (g_gen < target) __nanosleep(32);
            __threadfence();          // acquire
        }
    }
    __syncthreads();
}

// ---------------------------------------------------------------------------
// Kernel 2: persistent recurrent LSTM, split-K over two thread halves.
//   - 512 threads: tid = half*256 + b.  half 0: k in [0,336), half 1: [336,672)
//   - Each CTA owns HC=4 hidden units (NG=16 gate rows); weights resident
//     in SMEM (43 KB) for the whole kernel.
//   - Partial gate sums exchanged in 4 phases through a 4 KB smem buffer.
//   - c-state lives in half-0 thread registers.
// ---------------------------------------------------------------------------
__global__ void __launch_bounds__(512)
lstm_rec_kernel(const float* __restrict__ Wih,
                const float* __restrict__ Whh,
                const float* __restrict__ bih,
                const float* __restrict__ bhh,
                const float* __restrict__ c0) {
    __shared__ ulonglong2 wshv[DTOT * 4];   // 43008 B  (wf[k*16+u] = W_row(u)[k])
    __shared__ float      buf[4][B];        //  4096 B  partial exchange
    __shared__ float      bsh[NG];          //    64 B

    const int tid  = threadIdx.x;
    const int b    = tid & 255;             // batch index
    const int half = tid >> 8;              // 0 or 1 (k-split)
    const int j0   = blockIdx.x * HC;       // first hidden unit of this CTA

    // ---- one-time weight load into SMEM ----
    {
        float* wf = reinterpret_cast<float*>(wshv);
        for (int idx = tid; idx < DTOT * NG; idx += 512) {
            int k = idx >> 4;
            int u = idx & 15;
            int r = (u >> 2) * H + j0 + (u & 3);
            wf[idx] = (k < DIN) ? Wih[(size_t)r * DIN + k]
                                : Whh[(size_t)r * H + (k - DIN)];
        }
    }
    if (tid < NG) {
        int u = tid;
        int r = (u >> 2) * H + j0 + (u & 3);
        bsh[u] = bih[r] + bhh[r];
    }
    __syncthreads();

    // c-state in half-0 registers
    float cst[HC];
    if (half == 0) {
        #pragma unroll
        for (int u = 0; u < HC; ++u)
            cst[u] = c0[(size_t)b * H + j0 + u];
    }

    // ---- time loop ----
    for (int t = 0; t < T; ++t) {
        unsigned long long acc[8];
        if (half == 0) {
            #pragma unroll
            for (int q = 0; q < 8; ++q)
                acc[q] = pack2(bsh[2 * q], bsh[2 * q + 1]);
        } else {
            #pragma unroll
            for (int q = 0; q < 8; ++q)
                acc[q] = 0ull;
        }

        const float* xp = g_XT  + (size_t)t * DIN * B + b;
        const float* hp = g_hall + (size_t)t * H   * B + b;

        if (half == 0) {
            // x part: global k = 0..159
            #pragma unroll 8
            for (int k = 0; k < DIN; ++k) {
                float v = __ldcg(xp + k * B);
                unsigned long long v2 = pack2(v, v);
                const ulonglong2* w = &wshv[k * 4];
                #pragma unroll
                for (int m = 0; m < 4; ++m) {
                    ulonglong2 ww = w[m];
                    fma2(acc[2 * m],     v2, ww.x);
                    fma2(acc[2 * m + 1], v2, ww.y);
                }
            }
            // h part: global k = 160..335  (h rows 0..175)
            #pragma unroll 8
            for (int k = 0; k < KSPLIT - DIN; ++k) {
                float v = __ldcg(hp + k * B);
                unsigned long long v2 = pack2(v, v);
                const ulonglong2* w = &wshv[(DIN + k) * 4];
                #pragma unroll
                for (int m = 0; m < 4; ++m) {
                    ulonglong2 ww = w[m];
                    fma2(acc[2 * m],     v2, ww.x);
                    fma2(acc[2 * m + 1], v2, ww.y);
                }
            }
        } else {
            // h part: global k = 336..671  (h rows 176..511)
            const float* hp2 = hp + (KSPLIT - DIN) * B;
            #pragma unroll 8
            for (int k = 0; k < KSPLIT; ++k) {
                float v = __ldcg(hp2 + k * B);
                unsigned long long v2 = pack2(v, v);
                const ulonglong2* w = &wshv[(KSPLIT + k) * 4];
                #pragma unroll
                for (int m = 0; m < 4; ++m) {
                    ulonglong2 ww = w[m];
                    fma2(acc[2 * m],     v2, ww.x);
                    fma2(acc[2 * m + 1], v2, ww.y);
                }
            }
        }

        // ---- combine halves: 4 phases of 4 gate rows through 4 KB buffer ----
        float gf[NG];
        if (half == 0) {
            #pragma unroll
            for (int q = 0; q < 8; ++q) {
                float2 p = unpack2(acc[q]);
                gf[2 * q]     = p.x;
                gf[2 * q + 1] = p.y;
            }
        }
        #pragma unroll
        for (int ph = 0; ph < 4; ++ph) {
            if (half == 1) {
                float2 a0 = unpack2(acc[2 * ph]);
                float2 a1 = unpack2(acc[2 * ph + 1]);
                buf[0][b] = a0.x;
                buf[1][b] = a0.y;
                buf[2][b] = a1.x;
                buf[3][b] = a1.y;
            }
            __syncthreads();
            if (half == 0) {
                gf[4 * ph + 0] += buf[0][b];
                gf[4 * ph + 1] += buf[1][b];
                gf[4 * ph + 2] += buf[2][b];
                gf[4 * ph + 3] += buf[3][b];
            }
            __syncthreads();
        }

        // ---- activations + state update (half 0 only) ----
        if (half == 0) {
            float* outp = g_hall + (size_t)(t + 1) * H * B + b;
            #pragma unroll
            for (int u = 0; u < HC; ++u) {
                float i_ = sigm(gf[u]);          // gate i : rows 0..3
                float f_ = sigm(gf[4 + u]);      // gate f : rows 4..7
                float gg = tanhf(gf[8 + u]);     // gate g : rows 8..11
                float o_ = sigm(gf[12 + u]);     // gate o : rows 12..15
                float c  = f_ * cst[u] + i_ * gg;
                float h  = o_ * tanhf(c);
                cst[u]   = c;
                outp[(j0 + u) * B] = h;
            }
        }

        grid_barrier((unsigned int)(t + 1));
    }
}

// ---------------------------------------------------------------------------
// Kernel 3: y[b][t] = h_{t+1} . W_out + b_out  (fully parallel, deterministic)
// ---------------------------------------------------------------------------
__global__ void yfinal_kernel(const float* __restrict__ wout,
                              const float* __restrict__ bout,
                              float* __restrict__ y) {
    __shared__ float ws[H];
    const int t = blockIdx.x;
    const int b = threadIdx.x;
    for (int j = threadIdx.x; j < H; j += 256) ws[j] = wout[j];
    __syncthreads();

    float s = bout[0];
    const float* hp = g_hall + (size_t)(t + 1) * H * B + b;
    #pragma unroll 8
    for (int j = 0; j < H; ++j)
        s += hp[(size_t)j * B] * ws[j];
    y[(size_t)b * T + t] = s;
}

// ---------------------------------------------------------------------------
// Launch
// ---------------------------------------------------------------------------
extern "C" void kernel_launch(void* const* d_in, const int* in_sizes, int n_in,
                              void* d_out, int out_size) {
    const float* obs  = (const float*)d_in[0];
    const float* act  = (const float*)d_in[1];
    const float* Wih  = (const float*)d_in[2];
    const float* Whh  = (const float*)d_in[3];
    const float* bih  = (const float*)d_in[4];
    const float* bhh  = (const float*)d_in[5];
    const float* Wout = (const float*)d_in[6];
    const float* bout = (const float*)d_in[7];
    const float* h0   = (const float*)d_in[8];
    const float* c0   = (const float*)d_in[9];
    float* y = (float*)d_out;

    prep_kernel<<<T, 256>>>(obs, act, h0);
    lstm_rec_kernel<<<NCTA, 512>>>(Wih, Whh, bih, bhh, c0);
    yfinal_kernel<<<T, 256>>>(Wout, bout, y);
}